// round 17
// baseline (speedup 1.0000x reference)
#include <cuda_runtime.h>
#include <cuda_bf16.h>
#include <cstdint>

#define BS 128
#define NR 3
#define CD 64
#define CG 3
#define CH 256
#define KIN 67
#define HW 1024
#define PXT 32
#define THREADS 256
#define NBLK (BS * HW / PXT)   // 4096

#define XSTR 44          // row stride (u32 words); ldmatrix-phase conflict-free

// smem (u32 words)
#define SW_OFF   0                    // W bf16 [256][44]  = 11264
#define SX_OFF   11264                // X bf16 [96 rows][44] = 4224
#define W3_OFF   15488                // 256 f32
#define SRED_OFF 15744                // [4 nq][96] f32 = 384
#define WNM_OFF  16128                // [3][32] f32 = 96
#define SMEM_U32 16224
#define SMEM_BYTES (SMEM_U32 * 4)     // 64896

__device__ __forceinline__ void mma16(float* d, const uint32_t* a, uint32_t b0, uint32_t b1) {
    asm volatile(
        "mma.sync.aligned.m16n8k16.row.col.f32.bf16.bf16.f32 "
        "{%0,%1,%2,%3}, {%4,%5,%6,%7}, {%8,%9}, {%0,%1,%2,%3};"
        : "+f"(d[0]), "+f"(d[1]), "+f"(d[2]), "+f"(d[3])
        : "r"(a[0]), "r"(a[1]), "r"(a[2]), "r"(a[3]), "r"(b0), "r"(b1));
}
__device__ __forceinline__ void ldsm4(uint32_t* r, uint32_t addr) {
    asm volatile("ldmatrix.sync.aligned.m8n8.x4.shared.b16 {%0,%1,%2,%3}, [%4];"
        : "=r"(r[0]), "=r"(r[1]), "=r"(r[2]), "=r"(r[3]) : "r"(addr));
}
__device__ __forceinline__ uint32_t packbf(float lo, float hi) {
    __nv_bfloat162 v = __floats2bfloat162_rn(lo, hi);
    return *(uint32_t*)&v;
}
__device__ __forceinline__ uint32_t hmax2z(uint32_t v) {
    uint32_t r;
    asm("max.bf16x2 %0, %1, %2;" : "=r"(r) : "r"(v), "r"(0u));
    return r;
}

extern __shared__ uint32_t smu[];

__global__ __launch_bounds__(THREADS, 2)
void qnn_kernel(const float* __restrict__ data, const float* __restrict__ gt,
                const float* __restrict__ W1, const float* __restrict__ b1,
                const float* __restrict__ W3, const float* __restrict__ b3,
                float* __restrict__ out)
{
    uint32_t* sW = smu + SW_OFF;
    uint32_t* sX = smu + SX_OFF;
    float* w3s  = (float*)(smu + W3_OFF);
    float* sred = (float*)(smu + SRED_OFF);
    float* wnm  = (float*)(smu + WNM_OFF);

    const int tid  = threadIdx.x;
    const int lane = tid & 31;
    const int warp = tid >> 5;       // 0..7
    const int mw = warp & 1;         // row block of 48 (of 96 combined rows)
    const int nq = warp >> 1;        // output quarter (64 outs)
    const int g  = lane >> 2;        // 0..7
    const int tg = lane & 3;         // 0..3
    const int b  = blockIdx.x >> 5;
    const int p0 = (blockIdx.x & 31) * PXT;

    // ---- stage W main (k<64): canonical words, wd=lane -> conflict-free ----
    {
        const int wd = lane;                 // word = k pair (2wd, 2wd+1)
        const float* wbase = W1 + 2 * wd;
        #pragma unroll 1
        for (int ot = 0; ot < 4; ot++) {
            uint32_t pv[8]; int nn[8];
            #pragma unroll
            for (int j = 0; j < 8; j++) {
                int n = (ot * 8 + j) * 8 + warp;
                const float* wp = wbase + n * KIN;
                pv[j] = packbf(wp[0], wp[1]);
                nn[j] = n;
            }
            #pragma unroll
            for (int j = 0; j < 8; j++) sW[nn[j] * XSTR + wd] = pv[j];
        }
    }
    // ---- W tail: k=64..67 + zero pad (words 32..39) ----
    {
        int n = tid;
        const float* wp = W1 + n * KIN;
        float w64 = wp[64], w65 = wp[65], w66 = wp[66], bb = b1[n];
        uint4 u0, u1;
        u0.x = packbf(w64, w65); u0.y = packbf(w66, bb); u0.z = 0u; u0.w = 0u;
        u1.x = 0u; u1.y = 0u; u1.z = 0u; u1.w = 0u;
        *(uint4*)(sW + n * XSTR + 32) = u0;
        *(uint4*)(sW + n * XSTR + 36) = u1;
        w3s[n] = W3[n];
    }

    // ---- stage X main (k<64): rows r = n*32+px, 3 uint4/thread, batched ----
    {
        float v[3][8]; int rowoff[3];
        #pragma unroll
        for (int j = 0; j < 3; j++) {
            int i = j * THREADS + tid;        // < 768
            int px = i & 31, q = i >> 5;      // q 0..23
            int n = q >> 3, w4 = q & 7;
            int k0 = w4 * 8;
            const float* dp = data + ((size_t)(b * NR + n) * CD + k0) * HW + p0 + px;
            #pragma unroll
            for (int c = 0; c < 8; c++) v[j][c] = dp[(size_t)c * HW];
            rowoff[j] = (n * PXT + px) * XSTR + w4 * 4;
        }
        #pragma unroll
        for (int j = 0; j < 3; j++) {
            uint4 u;
            u.x = packbf(v[j][0], v[j][1]);
            u.y = packbf(v[j][2], v[j][3]);
            u.z = packbf(v[j][4], v[j][5]);
            u.w = packbf(v[j][6], v[j][7]);
            *(uint4*)(sX + rowoff[j]) = u;
        }
    }
    // ---- X tail: gt (k=64..66) + bias + zero pad ----
    if (tid < 96) {
        int n = tid >> 5, px = tid & 31;
        float g0 = gt[((size_t)b * CG + 0) * HW + p0 + px];
        float g1 = gt[((size_t)b * CG + 1) * HW + p0 + px];
        float g2 = gt[((size_t)b * CG + 2) * HW + p0 + px];
        uint4 u0, u1;
        u0.x = packbf(g0, g1); u0.y = packbf(g2, 1.0f); u0.z = 0u; u0.w = 0u;
        u1.x = 0u; u1.y = 0u; u1.z = 0u; u1.w = 0u;
        uint32_t* row = sX + (n * PXT + px) * XSTR;
        *(uint4*)(row + 32) = u0;
        *(uint4*)(row + 36) = u1;
    }
    const float bias3 = b3[0];
    __syncthreads();

    // ---- precompute w3 B-fragments (replicated over n): once ----
    uint32_t wb[4][2];
    #pragma unroll
    for (int p = 0; p < 4; p++) {
        int o0 = nq * 64 + p * 16 + tg * 2;
        wb[p][0] = packbf(w3s[o0],     w3s[o0 + 1]);
        wb[p][1] = packbf(w3s[o0 + 8], w3s[o0 + 9]);
    }

    // ---- ldmatrix lane addresses ----
    uint32_t sb;
    asm("{ .reg .u64 t; cvta.to.shared.u64 t, %1; cvt.u32.u64 %0, t; }"
        : "=r"(sb) : "l"(smu));
    const int t4 = lane >> 3;
    const int lr = lane & 7;
    uint32_t arA[3];
    #pragma unroll
    for (int mt = 0; mt < 3; mt++)
        arA[mt] = sb + (uint32_t)((SX_OFF +
                  (mw * 48 + mt * 16 + (t4 & 1) * 8 + lr) * XSTR + (t4 >> 1) * 4) * 4);
    uint32_t arB[4];
    #pragma unroll
    for (int j = 0; j < 4; j++)
        arB[j] = sb + (uint32_t)((SW_OFF +
                 (nq * 64 + (j * 2 + (t4 >> 1)) * 8 + lr) * XSTR + (t4 & 1) * 4) * 4);

    // ---- single merged GEMM: [96 rows] x [256 outs], B loaded once ----
    float acc[3][8][4];
    #pragma unroll
    for (int mt = 0; mt < 3; mt++)
        #pragma unroll
        for (int nt = 0; nt < 8; nt++)
            #pragma unroll
            for (int e = 0; e < 4; e++) acc[mt][nt][e] = 0.f;

    #pragma unroll
    for (int k16 = 0; k16 < 5; k16++) {
        uint32_t a[3][4];
        ldsm4(a[0], arA[0]);  arA[0] += 32;
        ldsm4(a[1], arA[1]);  arA[1] += 32;
        ldsm4(a[2], arA[2]);  arA[2] += 32;
        #pragma unroll
        for (int j = 0; j < 4; j++) {
            uint32_t bt[4];
            ldsm4(bt, arB[j]);  arB[j] += 32;
            #pragma unroll
            for (int mt = 0; mt < 3; mt++) {
                mma16(acc[mt][2 * j],     a[mt], bt[0], bt[1]);
                mma16(acc[mt][2 * j + 1], a[mt], bt[2], bt[3]);
            }
        }
    }

    // ---- epilogue as second MMA: s = relu(acc) @ w3 ----
    float sd[3][4];
    #pragma unroll
    for (int mt = 0; mt < 3; mt++)
        #pragma unroll
        for (int e = 0; e < 4; e++) sd[mt][e] = 0.f;

    #pragma unroll
    for (int p = 0; p < 4; p++) {
        #pragma unroll
        for (int mt = 0; mt < 3; mt++) {
            uint32_t a[4];
            a[0] = hmax2z(packbf(acc[mt][2 * p][0],     acc[mt][2 * p][1]));
            a[1] = hmax2z(packbf(acc[mt][2 * p][2],     acc[mt][2 * p][3]));
            a[2] = hmax2z(packbf(acc[mt][2 * p + 1][0], acc[mt][2 * p + 1][1]));
            a[3] = hmax2z(packbf(acc[mt][2 * p + 1][2], acc[mt][2 * p + 1][3]));
            mma16(sd[mt], a, wb[p][0], wb[p][1]);
        }
    }
    if (tg == 0) {
        #pragma unroll
        for (int mt = 0; mt < 3; mt++) {
            sred[nq * 96 + mw * 48 + mt * 16 + g]     = sd[mt][0];
            sred[nq * 96 + mw * 48 + mt * 16 + 8 + g] = sd[mt][2];
        }
    }
    __syncthreads();

    // ---- sigmoid + normalize ----
    if (tid < 32) {
        int px = tid;
        float t0 = 0.f, t1 = 0.f, t2 = 0.f;
        #pragma unroll
        for (int o4 = 0; o4 < 4; o4++) {
            t0 += sred[o4 * 96 +       px];
            t1 += sred[o4 * 96 + 32  + px];
            t2 += sred[o4 * 96 + 64  + px];
        }
        float g0 = 1.f / (1.f + __expf(-(t0 + bias3)));
        float g1 = 1.f / (1.f + __expf(-(t1 + bias3)));
        float g2 = 1.f / (1.f + __expf(-(t2 + bias3)));
        float inv = 1.f / (g0 + g1 + g2);
        wnm[px] = g0 * inv; wnm[32 + px] = g1 * inv; wnm[64 + px] = g2 * inv;
    }
    __syncthreads();

    // ---- w output: vectorized STG.128 ----
    if (tid < 24) {
        int n = tid >> 3, px4 = tid & 7;
        float4 v = *(const float4*)(wnm + n * 32 + px4 * 4);
        float* out_w = out + (size_t)BS * CD * HW;
        *(float4*)(out_w + ((size_t)b * NR + n) * HW + p0 + px4 * 4) = v;
    }

    // ---- z epilogue: vectorized (float4 over px), exact fp32 data ----
    {
        int px4 = tid & 7, cg = tid >> 3;       // 2 channels per thread
        const float* wb4 = wnm + px4 * 4;
        float4 w0 = *(const float4*)(wb4);
        float4 w1 = *(const float4*)(wb4 + 32);
        float4 w2 = *(const float4*)(wb4 + 64);
        const float* dbase = data + ((size_t)(b * NR) * CD + cg * 2) * HW + p0 + px4 * 4;
        float* obase = out + ((size_t)b * CD + cg * 2) * HW + p0 + px4 * 4;
        float4 v0[2], v1[2], v2[2];
        #pragma unroll
        for (int cc = 0; cc < 2; cc++) {
            v0[cc] = *(const float4*)(dbase + (size_t)(0 * CD + cc) * HW);
            v1[cc] = *(const float4*)(dbase + (size_t)(1 * CD + cc) * HW);
            v2[cc] = *(const float4*)(dbase + (size_t)(2 * CD + cc) * HW);
        }
        #pragma unroll
        for (int cc = 0; cc < 2; cc++) {
            float4 z;
            z.x = fmaf(v2[cc].x, w2.x, fmaf(v1[cc].x, w1.x, v0[cc].x * w0.x));
            z.y = fmaf(v2[cc].y, w2.y, fmaf(v1[cc].y, w1.y, v0[cc].y * w0.y));
            z.z = fmaf(v2[cc].z, w2.z, fmaf(v1[cc].z, w1.z, v0[cc].z * w0.z));
            z.w = fmaf(v2[cc].w, w2.w, fmaf(v1[cc].w, w1.w, v0[cc].w * w0.w));
            *(float4*)(obase + (size_t)cc * HW) = z;
        }
    }
}

extern "C" void kernel_launch(void* const* d_in, const int* in_sizes, int n_in,
                              void* d_out, int out_size) {
    const float* data = (const float*)d_in[0];
    const float* gt   = (const float*)d_in[1];
    const float* W1   = (const float*)d_in[2];
    const float* b1   = (const float*)d_in[3];
    const float* W3   = (const float*)d_in[4];
    const float* b3   = (const float*)d_in[5];
    float* out = (float*)d_out;

    cudaFuncSetAttribute(qnn_kernel, cudaFuncAttributeMaxDynamicSharedMemorySize,
                         SMEM_BYTES);
    qnn_kernel<<<NBLK, THREADS, SMEM_BYTES>>>(data, gt, W1, b1, W3, b3, out);
}